// round 3
// baseline (speedup 1.0000x reference)
#include <cuda_runtime.h>
#include <cstdint>

#define BATCH 8
#define CH    16
#define HH    256
#define WW    256
#define HW    (HH*WW)
#define NPTS  (BATCH*HH*WW)            // 524288 grid points
#define SCRATCH_F4 (NPTS*4)            // [b][i][j][c]: 2,097,152 float4 = 33.5 MB

// Scratch accumulator, channels innermost: scratch[b][i][j][c].
// Zero-initialized at module load; transpose_kernel restores zeros each call,
// so no explicit zeroing pass is needed and every call is deterministic.
__device__ float4 g_scratch4[SCRATCH_F4];

__device__ __forceinline__ float getc(const float4& v, int p) {
    return p == 0 ? v.x : p == 1 ? v.y : p == 2 ? v.z : v.w;
}

// ---------------------------------------------------------------------------
// Kernel 1: scatter. 4 consecutive (same-b) grid points per thread.
//   Per channel, the 4 points' x values are one contiguous float4 (w innermost).
//   Per point: 4 bilinear taps, each = 4x atomicAdd(float4) into scratch.
// ---------------------------------------------------------------------------
__global__ void __launch_bounds__(128) scatter_kernel(
    const float4* __restrict__ x4, const float4* __restrict__ grid4)
{
    int t = blockIdx.x * blockDim.x + threadIdx.x;   // 0 .. NPTS/4-1
    int b   = t >> 14;                               // (4t) >> 16
    int hw4 = t & 0x3FFF;                            // hw/4

    // grid: [b][h][w][2] float -> 4 points = 2 float4
    float4 ga = grid4[2 * t + 0];    // p0:(x,y) p1:(x,y)
    float4 gb = grid4[2 * t + 1];    // p2:(x,y) p3:(x,y)
    float gx[4] = {ga.x, ga.z, gb.x, gb.z};
    float gy[4] = {ga.y, ga.w, gb.y, gb.w};

    // x: [b][c][h][w]; one float4 per channel covers the 4 points.
    const float4* xp = x4 + ((size_t)b * (CH * HW) >> 2) + hw4;
    float4 xv[CH];
#pragma unroll
    for (int c = 0; c < CH; c++) xv[c] = xp[(size_t)c * (HW / 4)];

#pragma unroll
    for (int p = 0; p < 4; p++) {
        float ci = fminf(fmaxf((gx[p] + 1.0f) * 0.5f * 256.0f + 1.0f, 0.0f), 257.0f);
        float cj = fminf(fmaxf((gy[p] + 1.0f) * 0.5f * 256.0f + 1.0f, 0.0f), 257.0f);

        float fi0 = floorf(ci), fj0 = floorf(cj);
        int   i0 = (int)fi0,    j0 = (int)fj0;
        float fi = ci - fi0,    fj = cj - fj0;

        float wi[2] = {1.0f - fi, fi};
        float wj[2] = {1.0f - fj, fj};

#pragma unroll
        for (int di = 0; di < 2; di++) {
            int oi = i0 + di - 1;
            if ((unsigned)oi >= 256u) continue;
#pragma unroll
            for (int dj = 0; dj < 2; dj++) {
                int oj = j0 + dj - 1;
                if ((unsigned)oj >= 256u) continue;
                float wt = wi[di] * wj[dj];
                float4* dst = g_scratch4 + ((((size_t)b << 8 | oi) << 8 | oj) << 2);
#pragma unroll
                for (int k = 0; k < 4; k++) {
                    atomicAdd(dst + k,
                              make_float4(getc(xv[4*k + 0], p) * wt,
                                          getc(xv[4*k + 1], p) * wt,
                                          getc(xv[4*k + 2], p) * wt,
                                          getc(xv[4*k + 3], p) * wt));
                }
            }
        }
    }
}

// ---------------------------------------------------------------------------
// Kernel 2: transpose scratch [b][i][j][c] -> out [b][c][i][j], AND restore
// scratch to zero for the next call (each element read exactly once).
// One block per (b,i) row; smem stride-17 padding = conflict-free.
// ---------------------------------------------------------------------------
__global__ void __launch_bounds__(256) transpose_kernel(float* __restrict__ out) {
    __shared__ float s[256 * 17];
    int bi  = blockIdx.x;            // b*256 + i
    int tid = threadIdx.x;           // 0..255

    float4* src = g_scratch4 + (size_t)bi * (256 * 4);   // 1024 float4 per row
    const float4 z = make_float4(0.f, 0.f, 0.f, 0.f);
#pragma unroll
    for (int it = 0; it < 4; it++) {
        int e = it * 256 + tid;      // float4 index within row
        float4 v = src[e];
        src[e] = z;                  // restore zero for next call
        int j  = e >> 2;             // pixel column 0..255
        int cq = (e & 3) * 4;        // channel quad base 0/4/8/12
        float* sp = s + j * 17 + cq;
        sp[0] = v.x; sp[1] = v.y; sp[2] = v.z; sp[3] = v.w;
    }
    __syncthreads();

    int b = bi >> 8, i = bi & 255;
    float* op = out + ((size_t)b * CH * HH + i) * WW + tid;    // out[b][c][i][tid]
#pragma unroll
    for (int c = 0; c < CH; c++)
        op[(size_t)c * HW] = s[tid * 17 + c];                  // conflict-free
}

// ---------------------------------------------------------------------------
extern "C" void kernel_launch(void* const* d_in, const int* in_sizes, int n_in,
                              void* d_out, int out_size)
{
    const float* x    = (const float*)d_in[0];
    const float* grid = (const float*)d_in[1];
    if (in_sizes[0] != BATCH * CH * HW) {     // pick by size, defensively
        const float* t = x; x = grid; grid = t;
    }

    scatter_kernel<<<(NPTS / 4) / 128, 128>>>((const float4*)x, (const float4*)grid);
    transpose_kernel<<<BATCH * HH, 256>>>((float*)d_out);
}

// round 4
// speedup vs baseline: 1.1388x; 1.1388x over previous
#include <cuda_runtime.h>
#include <cstdint>

#define BATCH 8
#define CH    16
#define HH    256
#define WW    256
#define HW    (HH*WW)
#define NPTS  (BATCH*HH*WW)            // 524288 grid points
#define SCRATCH_F4 (NPTS*4)            // [b][i][j][c]: 2,097,152 float4 = 33.5 MB

// Scratch accumulator, channels innermost: scratch[b][i][j][c].
__device__ float4 g_scratch4[SCRATCH_F4];

// ---------------------------------------------------------------------------
// Kernel 1: zero the scratch accumulator (and pull it into L2).
// ---------------------------------------------------------------------------
__global__ void __launch_bounds__(256) zero_kernel() {
    int idx = blockIdx.x * blockDim.x + threadIdx.x;
    g_scratch4[idx] = make_float4(0.f, 0.f, 0.f, 0.f);
}

// ---------------------------------------------------------------------------
// Kernel 2: scatter. 2 consecutive (same-b) grid points per thread.
//   Per channel, the 2 points' x values are one contiguous float2.
//   Per point: 4 bilinear taps, each tap = 4x atomicAdd(float4) into scratch.
// ---------------------------------------------------------------------------
__global__ void __launch_bounds__(256) scatter_kernel(
    const float2* __restrict__ x2, const float4* __restrict__ grid4)
{
    int t = blockIdx.x * blockDim.x + threadIdx.x;   // 0 .. NPTS/2-1
    int b   = t >> 15;                               // (2t) >> 16
    int hw2 = t & 0x7FFF;                            // hw/2

    // grid: [b][h][w][2] -> 2 points = 1 float4: p0:(x,y) p1:(x,y)
    float4 g = grid4[t];
    float gx[2] = {g.x, g.z};
    float gy[2] = {g.y, g.w};

    // x: [b][c][h][w]; one float2 per channel covers both points.
    const float2* xp = x2 + ((size_t)b * (CH * HW) >> 1) + hw2;
    float2 xv[CH];
#pragma unroll
    for (int c = 0; c < CH; c++) xv[c] = xp[(size_t)c * (HW / 2)];

#pragma unroll
    for (int p = 0; p < 2; p++) {
        float ci = fminf(fmaxf((gx[p] + 1.0f) * 0.5f * 256.0f + 1.0f, 0.0f), 257.0f);
        float cj = fminf(fmaxf((gy[p] + 1.0f) * 0.5f * 256.0f + 1.0f, 0.0f), 257.0f);

        float fi0 = floorf(ci), fj0 = floorf(cj);
        int   i0 = (int)fi0,    j0 = (int)fj0;
        float fi = ci - fi0,    fj = cj - fj0;       // in [0,1)

        float wi[2] = {1.0f - fi, fi};
        float wj[2] = {1.0f - fj, fj};

#pragma unroll
        for (int di = 0; di < 2; di++) {
            int oi = i0 + di - 1;
            if ((unsigned)oi >= 256u) continue;
#pragma unroll
            for (int dj = 0; dj < 2; dj++) {
                int oj = j0 + dj - 1;
                if ((unsigned)oj >= 256u) continue;
                float wt = wi[di] * wj[dj];
                float4* dst = g_scratch4 + ((((size_t)b << 8 | oi) << 8 | oj) << 2);
#pragma unroll
                for (int k = 0; k < 4; k++) {
                    float v0 = (p == 0 ? xv[4*k + 0].x : xv[4*k + 0].y) * wt;
                    float v1 = (p == 0 ? xv[4*k + 1].x : xv[4*k + 1].y) * wt;
                    float v2 = (p == 0 ? xv[4*k + 2].x : xv[4*k + 2].y) * wt;
                    float v3 = (p == 0 ? xv[4*k + 3].x : xv[4*k + 3].y) * wt;
                    atomicAdd(dst + k, make_float4(v0, v1, v2, v3));
                }
            }
        }
    }
}

// ---------------------------------------------------------------------------
// Kernel 3: transpose scratch [b][i][j][c] -> out [b][c][i][j].
// One block per (b,i) row: load 256*16 floats coalesced (float4), stage in
// smem with stride-17 padding, write 16 coalesced 1KB channel segments.
// ---------------------------------------------------------------------------
__global__ void __launch_bounds__(256) transpose_kernel(float* __restrict__ out) {
    __shared__ float s[256 * 17];
    int bi  = blockIdx.x;            // b*256 + i
    int tid = threadIdx.x;           // 0..255

    const float4* src = g_scratch4 + (size_t)bi * (256 * 4);   // 1024 float4 per row
#pragma unroll
    for (int it = 0; it < 4; it++) {
        int e = it * 256 + tid;      // float4 index within row
        float4 v = src[e];
        int j  = e >> 2;             // pixel column 0..255
        int cq = (e & 3) * 4;        // channel quad base 0/4/8/12
        float* sp = s + j * 17 + cq;
        sp[0] = v.x; sp[1] = v.y; sp[2] = v.z; sp[3] = v.w;
    }
    __syncthreads();

    int b = bi >> 8, i = bi & 255;
    float* op = out + ((size_t)b * CH * HH + i) * WW + tid;    // out[b][c][i][tid]
#pragma unroll
    for (int c = 0; c < CH; c++)
        op[(size_t)c * HW] = s[tid * 17 + c];                  // conflict-free
}

// ---------------------------------------------------------------------------
extern "C" void kernel_launch(void* const* d_in, const int* in_sizes, int n_in,
                              void* d_out, int out_size)
{
    const float* x    = (const float*)d_in[0];
    const float* grid = (const float*)d_in[1];
    if (in_sizes[0] != BATCH * CH * HW) {     // pick by size, defensively
        const float* t = x; x = grid; grid = t;
    }

    zero_kernel<<<SCRATCH_F4 / 256, 256>>>();
    scatter_kernel<<<(NPTS / 2) / 256, 256>>>((const float2*)x, (const float4*)grid);
    transpose_kernel<<<BATCH * HH, 256>>>((float*)d_out);
}